// round 16
// baseline (speedup 1.0000x reference)
#include <cuda_runtime.h>
#include <cuda_bf16.h>
#include <math.h>
#include <stdint.h>

// ---------------------------------------------------------------------------
// Problem constants
// ---------------------------------------------------------------------------
#define B_SZ    2
#define L_SEQ   2048
#define D_MODEL 1024
#define D_INNER 2048
#define D_STATE 16
#define D_CONV  4
#define DT_RANK 64
#define NROW    (B_SZ * L_SEQ)           // 4096 rows n=(b,l)
#define E2      (2 * D_INNER)            // 4096
#define XDBL_W  (DT_RANK + 2 * D_STATE)  // 96
#define XSPLIT  8                        // split-K slices for x_proj

// ---------------------------------------------------------------------------
// Scratch (device globals; no cudaMalloc allowed)
// ---------------------------------------------------------------------------
__device__ __nv_bfloat16 g_h[(size_t)NROW * D_MODEL];       // LN out [n][d] bf16
__device__ float  g_xzT[(size_t)NROW * E2];                 // in_proj out [n][e] fp32
__device__ __nv_bfloat16 g_uct[(size_t)NROW * D_INNER];     // conv out [n][d] bf16 (GEMM)
__device__ float  g_ucf[(size_t)NROW * D_INNER];            // conv out [n][d] fp32 (scan)
__device__ float  g_xdbl[(size_t)NROW * XDBL_W];            // x_proj out fp32 (scan input)
__device__ __nv_bfloat16 g_xdbl_bf[(size_t)NROW * XDBL_W];  // bf16 copy (dt GEMM operand)
__device__ float  g_deltaT[(size_t)NROW * D_INNER];         // softplus(dt) [n][d] fp32
__device__ __nv_bfloat16 g_yt[(size_t)NROW * D_INNER];      // y*silu(z) [n][d] bf16
// bf16 weights (converted every launch)
__device__ __nv_bfloat16 g_win[(size_t)E2 * D_MODEL];
__device__ __nv_bfloat16 g_wx[(size_t)128 * D_INNER];       // 96 rows padded to 128
__device__ __nv_bfloat16 g_wdt[(size_t)D_INNER * DT_RANK];
__device__ __nv_bfloat16 g_wout[(size_t)D_MODEL * D_INNER];
// split-K partials for x_proj
__device__ float g_xpart[(size_t)XSPLIT * NROW * 128];

// ---------------------------------------------------------------------------
// low-level helpers
// ---------------------------------------------------------------------------
__device__ __forceinline__ void mma_bf16(float* d, const uint32_t* a, const uint32_t* b) {
    asm volatile(
        "mma.sync.aligned.m16n8k16.row.col.f32.bf16.bf16.f32 "
        "{%0,%1,%2,%3}, {%4,%5,%6,%7}, {%8,%9}, {%0,%1,%2,%3};\n"
        : "+f"(d[0]), "+f"(d[1]), "+f"(d[2]), "+f"(d[3])
        : "r"(a[0]), "r"(a[1]), "r"(a[2]), "r"(a[3]), "r"(b[0]), "r"(b[1]));
}
__device__ __forceinline__ void ldsm4(uint32_t* r, uint32_t saddr) {
    asm volatile("ldmatrix.sync.aligned.m8n8.x4.shared.b16 {%0,%1,%2,%3}, [%4];"
                 : "=r"(r[0]), "=r"(r[1]), "=r"(r[2]), "=r"(r[3]) : "r"(saddr));
}
__device__ __forceinline__ void cp_async16(uint32_t dst, const void* src) {
    asm volatile("cp.async.cg.shared.global [%0], [%1], 16;" :: "r"(dst), "l"(src));
}
__device__ __forceinline__ void cp_commit() {
    asm volatile("cp.async.commit_group;" ::: "memory");
}
template<int N> __device__ __forceinline__ void cp_wait() {
    asm volatile("cp.async.wait_group %0;" :: "n"(N) : "memory");
}

// ---------------------------------------------------------------------------
// bf16 mma.sync GEMM, cp.async 4-stage pipeline + ldmatrix fragments.
//   Ct[n][m] = sum_k Act[n][k] * W[m][k]   (+ epilogue per MODE)
// MODE 0: plain   MODE 1: +R[n][m]   MODE 2: softplus(v + R[m])
// MODE 3: split-K partial -> Ct + z*(NROW*128), kStart = z*kLen
// CTA tile 128(n) x 128(m), K-chunk 32 (bf16), 128 threads = 2(n) x 2(m)
// warps; warp tile 64x64 = 4x8 m16n8k16 tiles x 2 k-steps.
// ---------------------------------------------------------------------------
#define RS_B      80
#define TILE_B    (128 * RS_B)          // 10240 B per operand tile
#define STAGE_B   (2 * TILE_B)          // 20480 B per stage
#define GSMEM_BYTES (4 * STAGE_B)       // 81920 B (4 stages)

template<int MODE>
__global__ __launch_bounds__(128, 2)
void gemm_bf(const __nv_bfloat16* __restrict__ W, int ldw, int kLen,
             const __nv_bfloat16* __restrict__ Act, int ldact,
             float* __restrict__ Ct, int ldc,
             const float* __restrict__ R) {
    extern __shared__ __align__(16) char smem[];
    const uint32_t sbase = (uint32_t)__cvta_generic_to_shared(smem);
    const int tid    = threadIdx.x;
    const int lane   = tid & 31;
    const int wid    = tid >> 5;
    const int qid    = lane >> 2;
    const int qtid   = lane & 3;
    const int warp_m = wid & 1;      // act-row half (64 rows)
    const int warp_n = wid >> 1;     // feature half (64 feats)
    const int n0     = blockIdx.x * 128;
    const int m0     = blockIdx.y * 128;
    const int kStart = (MODE == 3) ? blockIdx.z * kLen : 0;
    if (MODE == 3) Ct += (size_t)blockIdx.z * NROW * 128;

    float acc[4][8][4];
#pragma unroll
    for (int mt = 0; mt < 4; mt++)
#pragma unroll
        for (int nt = 0; nt < 8; nt++)
#pragma unroll
            for (int q = 0; q < 4; q++) acc[mt][nt][q] = 0.0f;

    const int KI = kLen >> 5;

    auto stage = [&](int i, int buf) {
        const int k0 = kStart + (i << 5);
        const uint32_t sA = sbase + buf * STAGE_B;
        const uint32_t sB = sA + TILE_B;
#pragma unroll
        for (int jj = 0; jj < 4; jj++) {
            const int f   = jj * 128 + tid;
            const int row = f >> 2;
            const int seg = f & 3;
            cp_async16(sA + (uint32_t)(row * RS_B + seg * 16),
                       Act + (size_t)(n0 + row) * ldact + k0 + seg * 8);
            cp_async16(sB + (uint32_t)(row * RS_B + seg * 16),
                       W + (size_t)(m0 + row) * ldw + k0 + seg * 8);
        }
        cp_commit();
    };

    // ldmatrix lane offsets (bytes)
    const uint32_t aOff = (uint32_t)((warp_m * 64 + (lane & 7) + ((lane >> 3) & 1) * 8) * RS_B
                                     + (lane >> 4) * 16);
    const uint32_t bOff = (uint32_t)((warp_n * 64 + (lane & 7) + ((lane >> 4) & 1) * 8) * RS_B
                                     + ((lane >> 3) & 1) * 16);

    stage(0, 0);
    if (KI > 1) stage(1, 1);
    if (KI > 2) stage(2, 2);

    for (int i = 0; i < KI; i++) {
        if (i + 2 < KI)      cp_wait<2>();
        else if (i + 1 < KI) cp_wait<1>();
        else                 cp_wait<0>();
        __syncthreads();
        if (i + 3 < KI) stage(i + 3, (i + 3) & 3);

        const uint32_t aB = sbase + (i & 3) * STAGE_B;
        const uint32_t bB = aB + TILE_B;
#pragma unroll
        for (int ks = 0; ks < 2; ks++) {
            uint32_t af[4][4], bp[4][4];
#pragma unroll
            for (int mt = 0; mt < 4; mt++)
                ldsm4(af[mt], aB + aOff + (uint32_t)(mt * 16 * RS_B + ks * 32));
#pragma unroll
            for (int j = 0; j < 4; j++)
                ldsm4(bp[j], bB + bOff + (uint32_t)(j * 16 * RS_B + ks * 32));
#pragma unroll
            for (int mt = 0; mt < 4; mt++)
#pragma unroll
                for (int j = 0; j < 4; j++) {
                    mma_bf16(acc[mt][2 * j + 0], af[mt], &bp[j][0]);
                    mma_bf16(acc[mt][2 * j + 1], af[mt], &bp[j][2]);
                }
        }
        __syncthreads();
    }

    // epilogue: Ct[n][m] float2 stores
#pragma unroll
    for (int mt = 0; mt < 4; mt++) {
        const int n = n0 + warp_m * 64 + mt * 16 + qid;
#pragma unroll
        for (int nt = 0; nt < 8; nt++) {
            const int m = m0 + warp_n * 64 + nt * 8 + 2 * qtid;
            float2 v0 = make_float2(acc[mt][nt][0], acc[mt][nt][1]);
            float2 v1 = make_float2(acc[mt][nt][2], acc[mt][nt][3]);
            if (MODE == 1) {
                const float2 r0 = *(const float2*)(R + (size_t)n * ldc + m);
                const float2 r1 = *(const float2*)(R + (size_t)(n + 8) * ldc + m);
                v0.x += r0.x; v0.y += r0.y;
                v1.x += r1.x; v1.y += r1.y;
            } else if (MODE == 2) {
                const float2 bb = *(const float2*)(R + m);
                v0.x += bb.x; v0.y += bb.y; v1.x += bb.x; v1.y += bb.y;
                v0.x = (v0.x > 20.0f) ? v0.x : log1pf(expf(v0.x));
                v0.y = (v0.y > 20.0f) ? v0.y : log1pf(expf(v0.y));
                v1.x = (v1.x > 20.0f) ? v1.x : log1pf(expf(v1.x));
                v1.y = (v1.y > 20.0f) ? v1.y : log1pf(expf(v1.y));
            }
            *(float2*)(Ct + (size_t)n * ldc + m) = v0;
            *(float2*)(Ct + (size_t)(n + 8) * ldc + m) = v1;
        }
    }
}

// ---------------------------------------------------------------------------
// Weight convert fp32 -> bf16, zero-pad rows >= rowsValid.
// ---------------------------------------------------------------------------
__global__ void cvt_w_kernel(const float* __restrict__ src, __nv_bfloat16* __restrict__ dst,
                             int rowsValid, int cols, int total4) {
    const int i4 = blockIdx.x * 256 + threadIdx.x;
    if (i4 >= total4) return;
    const int i = i4 * 4;
    const int row = i / cols;
    float4 v = make_float4(0.f, 0.f, 0.f, 0.f);
    if (row < rowsValid) v = *(const float4*)(src + i);
    __nv_bfloat162 p01 = __floats2bfloat162_rn(v.x, v.y);
    __nv_bfloat162 p23 = __floats2bfloat162_rn(v.z, v.w);
    uint2 u = make_uint2(*(uint32_t*)&p01, *(uint32_t*)&p23);
    *(uint2*)(dst + i) = u;
}

// ---------------------------------------------------------------------------
// x_proj split-K reduce: fp32 xdbl (scan input) + bf16 copy (dt operand).
// ---------------------------------------------------------------------------
__global__ void reduce_x_kernel() {
    const int idx = blockIdx.x * 256 + threadIdx.x;   // over NROW*96
    if (idx >= NROW * XDBL_W) return;
    const int n = idx / XDBL_W;
    const int m = idx - n * XDBL_W;
    float s = 0.0f;
#pragma unroll
    for (int sl = 0; sl < XSPLIT; sl++)
        s += g_xpart[((size_t)sl * NROW + n) * 128 + m];
    g_xdbl[idx]    = s;
    g_xdbl_bf[idx] = __float2bfloat16_rn(s);
}

// ---------------------------------------------------------------------------
// LayerNorm: one block per row n; writes h[n][d] bf16.
// ---------------------------------------------------------------------------
__global__ void ln_kernel(const float* __restrict__ x,
                          const float* __restrict__ gamma,
                          const float* __restrict__ beta) {
    const int row = blockIdx.x;
    const int tid = threadIdx.x;           // 256
    const float4 v = *(const float4*)(x + (size_t)row * D_MODEL + tid * 4);

    float s  = v.x + v.y + v.z + v.w;
    float sq = v.x * v.x + v.y * v.y + v.z * v.z + v.w * v.w;

    __shared__ float red_s[8], red_q[8];
    for (int o = 16; o > 0; o >>= 1) {
        s  += __shfl_xor_sync(0xffffffffu, s, o);
        sq += __shfl_xor_sync(0xffffffffu, sq, o);
    }
    const int wid = tid >> 5, lid = tid & 31;
    if (lid == 0) { red_s[wid] = s; red_q[wid] = sq; }
    __syncthreads();
    if (wid == 0) {
        s  = red_s[lid & 7];
        sq = red_q[lid & 7];
        for (int o = 4; o > 0; o >>= 1) {
            s  += __shfl_xor_sync(0xffffffffu, s, o);
            sq += __shfl_xor_sync(0xffffffffu, sq, o);
        }
        if (lid == 0) { red_s[0] = s; red_q[0] = sq; }
    }
    __syncthreads();
    const float mean = red_s[0] * (1.0f / D_MODEL);
    const float var  = red_q[0] * (1.0f / D_MODEL) - mean * mean;
    const float rstd = rsqrtf(var + 1e-6f);

    const int d0 = tid * 4;
    const float4 g4 = *(const float4*)(gamma + d0);
    const float4 b4 = *(const float4*)(beta + d0);
    const float o0 = (v.x - mean) * rstd * g4.x + b4.x;
    const float o1 = (v.y - mean) * rstd * g4.y + b4.y;
    const float o2 = (v.z - mean) * rstd * g4.z + b4.z;
    const float o3 = (v.w - mean) * rstd * g4.w + b4.w;
    __nv_bfloat162 p01 = __floats2bfloat162_rn(o0, o1);
    __nv_bfloat162 p23 = __floats2bfloat162_rn(o2, o3);
    uint2 u = make_uint2(*(uint32_t*)&p01, *(uint32_t*)&p23);
    *(uint2*)(g_h + (size_t)row * D_MODEL + d0) = u;
}

// ---------------------------------------------------------------------------
// Depthwise causal conv(k=4)+bias+SiLU. Writes uct bf16 + ucf fp32, both [n][d].
// Tile: 32 d x 64 l per block. 256 threads. No transpose needed anymore.
// ---------------------------------------------------------------------------
__global__ __launch_bounds__(256)
void conv_kernel(const float* __restrict__ conv_w,
                 const float* __restrict__ conv_b) {
    __shared__ float s_in[67][33];
    const int tid = threadIdx.x;
    const int d0  = blockIdx.x * 32;
    const int l0  = blockIdx.y * 64;
    const int b   = blockIdx.z;

    for (int base = tid; base < 67 * 32; base += 256) {
        const int r = base >> 5;
        const int c = base & 31;
        const int l = l0 - 3 + r;
        float v = 0.0f;
        if (l >= 0) v = g_xzT[((size_t)b * L_SEQ + l) * E2 + d0 + c];
        s_in[r][c] = v;
    }
    __syncthreads();

    for (int base = tid; base < 64 * 32; base += 256) {
        const int ll = base >> 5;
        const int c  = base & 31;
        const int d  = d0 + c;
        const float4 w = *(const float4*)(conv_w + d * 4);
        float s = conv_b[d];
        s = fmaf(w.x, s_in[ll + 0][c], s);
        s = fmaf(w.y, s_in[ll + 1][c], s);
        s = fmaf(w.z, s_in[ll + 2][c], s);
        s = fmaf(w.w, s_in[ll + 3][c], s);
        const float v = s / (1.0f + expf(-s));
        const size_t nidx = ((size_t)b * L_SEQ + l0 + ll) * D_INNER + d;
        g_uct[nidx] = __float2bfloat16_rn(v);
        g_ucf[nidx] = v;
    }
}

// ---------------------------------------------------------------------------
// Selective scan v2. 4 lanes per channel, 4 states per lane.
// Fast path exploits A[d][n] = -exp(log(n+1)) ~= -(n+1):
//   deltaA_n = r^(n+1) with r = exp(-delta) -> 1 MUFU + mul ladder.
// Guarded: falls back to general expf path if A deviates.
// Fuses y = (scan + u*D) * silu(z), writes bf16 yt[n][d] directly.
// block = 64 threads (16 channels), grid = (D_INNER/16, B).
// ---------------------------------------------------------------------------
__global__ __launch_bounds__(64)
void scan_kernel(const float* __restrict__ A_log,
                 const float* __restrict__ Dvec) {
    const int lane = threadIdx.x & 31;
    const int w    = threadIdx.x >> 5;         // 0..1
    const int c    = lane >> 2;                // 0..7 channel within warp
    const int j    = lane & 3;                 // state quad index
    const int d    = blockIdx.x * 16 + w * 8 + c;
    const int b    = blockIdx.y;

    const float4 al = *(const float4*)(A_log + d * D_STATE + 4 * j);
    const float A0 = -expf(al.x), A1 = -expf(al.y), A2 = -expf(al.z), A3 = -expf(al.w);
    const float Dd = Dvec[d];

    // fast-path check: A_k == -(4j+1+k) within 1e-3 relative
    const float k0 = (float)(4 * j + 1);
    bool ok = (fabsf(-A0 - k0) < 1e-3f * k0) &&
              (fabsf(-A1 - (k0 + 1.0f)) < 1e-3f * (k0 + 1.0f)) &&
              (fabsf(-A2 - (k0 + 2.0f)) < 1e-3f * (k0 + 2.0f)) &&
              (fabsf(-A3 - (k0 + 3.0f)) < 1e-3f * (k0 + 3.0f));
    const bool fast = __all_sync(0xffffffffu, ok);

    const float* dp = g_deltaT + (size_t)b * L_SEQ * D_INNER + d;
    const float* up = g_ucf    + (size_t)b * L_SEQ * D_INNER + d;
    const float* zp = g_xzT    + (size_t)b * L_SEQ * E2 + D_INNER + d;
    const float* xb = g_xdbl   + (size_t)b * L_SEQ * XDBL_W + DT_RANK + 4 * j;
    __nv_bfloat16* yp = g_yt   + (size_t)b * L_SEQ * D_INNER + d;

    float s0 = 0.f, s1 = 0.f, s2 = 0.f, s3 = 0.f;

    if (fast) {
#pragma unroll 4
        for (int l = 0; l < L_SEQ; l++) {
            const float dv = __ldg(dp + (size_t)l * D_INNER);
            const float u  = __ldg(up + (size_t)l * D_INNER);
            const float zz = __ldg(zp + (size_t)l * E2);
            const float4 B4 = *(const float4*)(xb + (size_t)l * XDBL_W);
            const float4 C4 = *(const float4*)(xb + (size_t)l * XDBL_W + D_STATE);

            const float r  = __expf(-dv);
            const float r2 = r * r, r4 = r2 * r2, r8 = r4 * r4;
            float sp = (j & 1) ? r4 : 1.0f;
            if (j & 2) sp *= r8;
            const float dA0 = sp * r, dA1 = dA0 * r, dA2 = dA1 * r, dA3 = dA2 * r;

            const float dvu = dv * u;
            s0 = fmaf(dA0, s0, dvu * B4.x);
            s1 = fmaf(dA1, s1, dvu * B4.y);
            s2 = fmaf(dA2, s2, dvu * B4.z);
            s3 = fmaf(dA3, s3, dvu * B4.w);

            float yc = fmaf(s1, C4.y, s0 * C4.x) + fmaf(s3, C4.w, s2 * C4.z);
            yc += __shfl_xor_sync(0xffffffffu, yc, 1);
            yc += __shfl_xor_sync(0xffffffffu, yc, 2);

            if (j == 0) {
                const float sil = zz / (1.0f + __expf(-zz));
                yp[(size_t)l * D_INNER] = __float2bfloat16_rn((yc + u * Dd) * sil);
            }
        }
    } else {
#pragma unroll 4
        for (int l = 0; l < L_SEQ; l++) {
            const float dv = __ldg(dp + (size_t)l * D_INNER);
            const float u  = __ldg(up + (size_t)l * D_INNER);
            const float zz = __ldg(zp + (size_t)l * E2);
            const float4 B4 = *(const float4*)(xb + (size_t)l * XDBL_W);
            const float4 C4 = *(const float4*)(xb + (size_t)l * XDBL_W + D_STATE);

            const float dA0 = __expf(dv * A0), dA1 = __expf(dv * A1);
            const float dA2 = __expf(dv * A2), dA3 = __expf(dv * A3);

            const float dvu = dv * u;
            s0 = fmaf(dA0, s0, dvu * B4.x);
            s1 = fmaf(dA1, s1, dvu * B4.y);
            s2 = fmaf(dA2, s2, dvu * B4.z);
            s3 = fmaf(dA3, s3, dvu * B4.w);

            float yc = fmaf(s1, C4.y, s0 * C4.x) + fmaf(s3, C4.w, s2 * C4.z);
            yc += __shfl_xor_sync(0xffffffffu, yc, 1);
            yc += __shfl_xor_sync(0xffffffffu, yc, 2);

            if (j == 0) {
                const float sil = zz / (1.0f + __expf(-zz));
                yp[(size_t)l * D_INNER] = __float2bfloat16_rn((yc + u * Dd) * sil);
            }
        }
    }
}

// ---------------------------------------------------------------------------
// Launch
// ---------------------------------------------------------------------------
extern "C" void kernel_launch(void* const* d_in, const int* in_sizes, int n_in,
                              void* d_out, int out_size) {
    const float* x        = (const float*)d_in[0];
    const float* ln_gamma = (const float*)d_in[1];
    const float* ln_beta  = (const float*)d_in[2];
    const float* in_proj  = (const float*)d_in[3];
    const float* conv_w   = (const float*)d_in[4];
    const float* conv_b   = (const float*)d_in[5];
    const float* x_proj   = (const float*)d_in[6];
    const float* dt_proj  = (const float*)d_in[7];
    const float* dt_pb    = (const float*)d_in[8];
    const float* A_log    = (const float*)d_in[9];
    const float* Dvec     = (const float*)d_in[10];
    const float* out_proj = (const float*)d_in[11];
    float* out = (float*)d_out;

    float *xzT, *deltaT, *xpart, *xdbl;
    __nv_bfloat16 *h, *uct, *yt, *win, *wx, *wdt, *wout, *xdbl_bf;
    cudaGetSymbolAddress((void**)&h,       g_h);
    cudaGetSymbolAddress((void**)&xzT,     g_xzT);
    cudaGetSymbolAddress((void**)&uct,     g_uct);
    cudaGetSymbolAddress((void**)&xdbl,    g_xdbl);
    cudaGetSymbolAddress((void**)&xdbl_bf, g_xdbl_bf);
    cudaGetSymbolAddress((void**)&deltaT,  g_deltaT);
    cudaGetSymbolAddress((void**)&yt,      g_yt);
    cudaGetSymbolAddress((void**)&win,     g_win);
    cudaGetSymbolAddress((void**)&wx,      g_wx);
    cudaGetSymbolAddress((void**)&wdt,     g_wdt);
    cudaGetSymbolAddress((void**)&wout,    g_wout);
    cudaGetSymbolAddress((void**)&xpart,   g_xpart);

    static bool attr_set = false;
    if (!attr_set) {
        cudaFuncSetAttribute(gemm_bf<0>, cudaFuncAttributeMaxDynamicSharedMemorySize, GSMEM_BYTES);
        cudaFuncSetAttribute(gemm_bf<1>, cudaFuncAttributeMaxDynamicSharedMemorySize, GSMEM_BYTES);
        cudaFuncSetAttribute(gemm_bf<2>, cudaFuncAttributeMaxDynamicSharedMemorySize, GSMEM_BYTES);
        cudaFuncSetAttribute(gemm_bf<3>, cudaFuncAttributeMaxDynamicSharedMemorySize, GSMEM_BYTES);
        attr_set = true;
    }

    // 0. convert weights to bf16
    {
        int t;
        t = E2 * D_MODEL / 4;
        cvt_w_kernel<<<(t + 255) / 256, 256>>>(in_proj, win, E2, D_MODEL, t);
        t = 128 * D_INNER / 4;
        cvt_w_kernel<<<(t + 255) / 256, 256>>>(x_proj, wx, XDBL_W, D_INNER, t);
        t = D_INNER * DT_RANK / 4;
        cvt_w_kernel<<<(t + 255) / 256, 256>>>(dt_proj, wdt, D_INNER, DT_RANK, t);
        t = D_MODEL * D_INNER / 4;
        cvt_w_kernel<<<(t + 255) / 256, 256>>>(out_proj, wout, D_MODEL, D_INNER, t);
    }

    // 1. LayerNorm -> h[n][d] bf16
    ln_kernel<<<NROW, 256>>>(x, ln_gamma, ln_beta);

    // 2. in_proj: xzT[n][e] = h[n][:] . Win[e][:]
    gemm_bf<0><<<dim3(NROW / 128, E2 / 128), 128, GSMEM_BYTES>>>(
        win, D_MODEL, D_MODEL, h, D_MODEL, xzT, E2, nullptr);

    // 3. conv + SiLU -> uct bf16 + ucf fp32, both [n][d]
    conv_kernel<<<dim3(D_INNER / 32, L_SEQ / 64, B_SZ), 256>>>(conv_w, conv_b);

    // 4. x_proj split-K partials, then reduce -> xdbl (fp32 + bf16)
    gemm_bf<3><<<dim3(NROW / 128, 1, XSPLIT), 128, GSMEM_BYTES>>>(
        wx, D_INNER, D_INNER / XSPLIT, uct, D_INNER, xpart, 128, nullptr);
    reduce_x_kernel<<<(NROW * XDBL_W + 255) / 256, 256>>>();

    // 5. dt_proj (tensor) + bias + softplus -> deltaT[n][d] fp32
    gemm_bf<2><<<dim3(NROW / 128, D_INNER / 128), 128, GSMEM_BYTES>>>(
        wdt, DT_RANK, DT_RANK, xdbl_bf, XDBL_W, deltaT, D_INNER, dt_pb);

    // 6. selective scan (fused silu(z) multiply) -> yt[n][d] bf16
    scan_kernel<<<dim3(D_INNER / 16, B_SZ), 64>>>(A_log, Dvec);

    // 7. out_proj + residual: out[n][e] = yt[n][:] . Wout[e][:] + x
    gemm_bf<1><<<dim3(NROW / 128, D_MODEL / 128), 128, GSMEM_BYTES>>>(
        wout, D_INNER, D_INNER, yt, D_INNER, out, D_MODEL, x);
}